// round 6
// baseline (speedup 1.0000x reference)
#include <cuda_runtime.h>
#include <cstdint>
#include <math.h>

#define T_ 2048
#define B_ 2
#define C_ 512
#define H_ 16
#define HD_ 32
#define NEG_INF_ (-1e30f)

// ---------------- scratch (device globals; no allocation allowed) ----------------
__device__ float    g_logw[T_];
__device__ uint32_t g_mask[T_ * (T_ / 32)];
__device__ float    g_q[B_ * H_ * T_ * HD_];
__device__ float    g_k[B_ * H_ * T_ * HD_];
__device__ float    g_v[B_ * H_ * T_ * HD_];
__device__ float    g_ao[B_ * T_ * C_];

// ---------------- threefry2x32 (exact JAX replication) ----------------
__device__ __forceinline__ uint32_t rotl32(uint32_t v, int r) {
    return (v << r) | (v >> (32 - r));
}

__device__ __forceinline__ void threefry2x32(uint32_t k0, uint32_t k1,
                                             uint32_t& x0, uint32_t& x1) {
    uint32_t k2 = k0 ^ k1 ^ 0x1BD11BDAu;
    x0 += k0; x1 += k1;
#define RND_(r) { x0 += x1; x1 = rotl32(x1, (r)); x1 ^= x0; }
    RND_(13) RND_(15) RND_(26) RND_(6)
    x0 += k1; x1 += k2 + 1u;
    RND_(17) RND_(29) RND_(16) RND_(24)
    x0 += k2; x1 += k0 + 2u;
    RND_(13) RND_(15) RND_(26) RND_(6)
    x0 += k0; x1 += k1 + 3u;
    RND_(17) RND_(29) RND_(16) RND_(24)
    x0 += k1; x1 += k2 + 4u;
    RND_(13) RND_(15) RND_(26) RND_(6)
    x0 += k2; x1 += k0 + 5u;
#undef RND_
}

// ---------------- kernel 0: logw = log(softmax(grad*100)) ----------------
__global__ void logw_kernel(const float* __restrict__ grad) {
    __shared__ float red[256];
    int t = threadIdx.x;
    float m = -3.4e38f;
    for (int j = t; j < T_; j += 256) m = fmaxf(m, grad[j] * 100.0f);
    red[t] = m; __syncthreads();
    for (int s = 128; s > 0; s >>= 1) {
        if (t < s) red[t] = fmaxf(red[t], red[t + s]);
        __syncthreads();
    }
    m = red[0]; __syncthreads();
    float sum = 0.f;
    for (int j = t; j < T_; j += 256) sum += expf(grad[j] * 100.0f - m);
    red[t] = sum; __syncthreads();
    for (int s = 128; s > 0; s >>= 1) {
        if (t < s) red[t] += red[t + s];
        __syncthreads();
    }
    sum = red[0];
    for (int j = t; j < T_; j += 256) {
        float p = expf(grad[j] * 100.0f - m) / sum;
        g_logw[j] = logf(p);
    }
}

// ---------------- kernel 1: per-row gumbel top-k mask (exact, partitionable threefry) ----------------
__global__ void mask_kernel(int n_extra) {
    __shared__ uint32_t sk[T_];
    __shared__ uint32_t hist[256];
    __shared__ uint32_t mbits[T_ / 32];
    __shared__ uint32_t s_prefix;
    __shared__ int s_krem;

    int i = blockIdx.x;      // query row
    int t = threadIdx.x;

    // ordered-uint keys of logw + gumbel (band -> -inf)
    for (int j = t; j < T_; j += 256) {
        int dd = j - i;
        float val;
        if (dd >= -1 && dd <= 1) {
            val = -INFINITY;
        } else {
            // JAX partitionable threefry random_bits:
            //   counts = iota(u64);  (x0,x1) = (hi32, lo32) = (0, m)
            //   bits32 = out0 ^ out1
            uint32_t m = (uint32_t)i * (uint32_t)T_ + (uint32_t)j;
            uint32_t a = 0u;
            uint32_t b = m;
            threefry2x32(0u, 42u, a, b);
            uint32_t bits = a ^ b;
            uint32_t fb = (bits >> 9) | 0x3f800000u;
            float f = __uint_as_float(fb) - 1.0f;
            float u = fmaxf(1.17549435e-38f, f);   // jax uniform(minval=tiny)
            float g = -logf(-logf(u));
            val = g_logw[j] + g;
        }
        uint32_t ob = __float_as_uint(val);
        ob = (ob & 0x80000000u) ? ~ob : (ob | 0x80000000u);
        sk[j] = ob;
    }
    for (int w = t; w < T_ / 32; w += 256) mbits[w] = 0u;
    __syncthreads();

    // radix-select the n_extra-th largest key
    uint32_t prefix = 0u, pmask = 0u;
    int krem = n_extra;
    for (int shift = 24; shift >= 0; shift -= 8) {
        hist[t] = 0u;
        __syncthreads();
        for (int j = t; j < T_; j += 256) {
            uint32_t key = sk[j];
            if ((key & pmask) == prefix)
                atomicAdd(&hist[(key >> shift) & 0xFFu], 1u);
        }
        __syncthreads();
        if (t == 0) {
            int acc = 0; int d = 255;
            for (; d > 0; d--) {
                int h = (int)hist[d];
                if (acc + h >= krem) break;
                acc += h;
            }
            s_prefix = prefix | ((uint32_t)d << shift);
            s_krem = krem - acc;
        }
        __syncthreads();
        prefix = s_prefix; krem = s_krem;
        pmask |= (0xFFu << shift);
        __syncthreads();
    }
    uint32_t vstar = prefix;

    // mark strictly-greater values + band, apply causal
    for (int j = t; j < T_; j += 256) {
        int dd = j - i;
        bool band = (dd >= -1 && dd <= 1);
        if ((band || sk[j] > vstar) && j <= i)
            atomicOr(&mbits[j >> 5], 1u << (j & 31));
    }
    __syncthreads();
    // stable (lower-index-first) selection among ties at the threshold
    if (t == 0) {
        int need = krem;
        for (int j = 0; j < T_ && need > 0; j++) {
            if (sk[j] == vstar) {
                need--;
                if (j <= i) mbits[j >> 5] |= (1u << (j & 31));
            }
        }
    }
    __syncthreads();
    for (int w = t; w < T_ / 32; w += 256)
        g_mask[i * (T_ / 32) + w] = mbits[w];
}

// ---------------- kernel 2: tiled fp32 GEMM Y[4096,512] = X[4096,512] @ W[512,512] ----------------
// mode 0: Y row-major [M,C].  mode 1: scatter to [B,H,T,HD] layout.
__global__ void gemm_kernel(const float* __restrict__ X, const float* __restrict__ W,
                            float* __restrict__ Y, int mode) {
    __shared__ float Xs[64][17];
    __shared__ __align__(16) float Ws[16][64];
    int tid = threadIdx.x;
    int tx = tid & 15, ty = tid >> 4;
    int m0 = blockIdx.y * 64, n0 = blockIdx.x * 64;

    float acc[4][4] = {};

    for (int k0 = 0; k0 < C_; k0 += 16) {
        for (int idx = tid; idx < 64 * 16; idx += 256) {
            int r = idx >> 4, c = idx & 15;
            Xs[r][c] = X[(size_t)(m0 + r) * C_ + k0 + c];
        }
        for (int idx = tid; idx < 16 * 64; idx += 256) {
            int r = idx >> 6, c = idx & 63;
            Ws[r][c] = W[(size_t)(k0 + r) * C_ + n0 + c];
        }
        __syncthreads();
#pragma unroll
        for (int kk = 0; kk < 16; kk++) {
            float a0 = Xs[ty * 4 + 0][kk];
            float a1 = Xs[ty * 4 + 1][kk];
            float a2 = Xs[ty * 4 + 2][kk];
            float a3 = Xs[ty * 4 + 3][kk];
            float4 b4 = *(const float4*)&Ws[kk][tx * 4];
            float b[4] = {b4.x, b4.y, b4.z, b4.w};
#pragma unroll
            for (int c = 0; c < 4; c++) {
                acc[0][c] += a0 * b[c];
                acc[1][c] += a1 * b[c];
                acc[2][c] += a2 * b[c];
                acc[3][c] += a3 * b[c];
            }
        }
        __syncthreads();
    }

#pragma unroll
    for (int r = 0; r < 4; r++) {
#pragma unroll
        for (int c = 0; c < 4; c++) {
            int m = m0 + ty * 4 + r;
            int n = n0 + tx * 4 + c;
            if (mode == 1) {
                int b = m >> 11;           // m / T_
                int tt = m & (T_ - 1);
                int h = n >> 5;            // n / HD_
                int d = n & (HD_ - 1);
                Y[(((size_t)(b * H_ + h)) * T_ + tt) * HD_ + d] = acc[r][c];
            } else {
                Y[(size_t)m * C_ + n] = acc[r][c];
            }
        }
    }
}

// ---------------- kernel 3: masked flash attention (fp32) ----------------
__global__ void attn_kernel() {
    int qt = blockIdx.x;       // query tile (64 queries)
    int bh = blockIdx.y;       // b*H + h
    const float* qp = g_q + (size_t)bh * T_ * HD_ + (size_t)qt * 64 * HD_;
    const float* kp = g_k + (size_t)bh * T_ * HD_;
    const float* vp = g_v + (size_t)bh * T_ * HD_;

    __shared__ float Qs[64][33];
    __shared__ float Ks[64][33];
    __shared__ float Vs[64][33];
    __shared__ float Ps[64][65];

    int tid = threadIdx.x;
    int tx = tid & 15, ty = tid >> 4;

    for (int idx = tid; idx < 64 * 32; idx += 256)
        Qs[idx >> 5][idx & 31] = qp[idx];

    float acc[4][2] = {};
    float mr[4], lr[4];
#pragma unroll
    for (int r = 0; r < 4; r++) { mr[r] = NEG_INF_; lr[r] = 0.f; }

    const float scale = 0.17677669529663687f;  // 1/sqrt(32)
    int q0 = qt * 64;

    for (int kt = 0; kt <= qt; kt++) {
        for (int idx = tid; idx < 64 * 32; idx += 256) {
            int j = idx >> 5, d = idx & 31;
            Ks[j][d] = kp[(size_t)(kt * 64) * HD_ + idx];
            Vs[j][d] = vp[(size_t)(kt * 64) * HD_ + idx];
        }
        __syncthreads();

        float s[4][4] = {};
#pragma unroll
        for (int d = 0; d < 32; d++) {
            float a0 = Qs[ty * 4 + 0][d];
            float a1 = Qs[ty * 4 + 1][d];
            float a2 = Qs[ty * 4 + 2][d];
            float a3 = Qs[ty * 4 + 3][d];
            float b0 = Ks[tx * 4 + 0][d];
            float b1 = Ks[tx * 4 + 1][d];
            float b2 = Ks[tx * 4 + 2][d];
            float b3 = Ks[tx * 4 + 3][d];
            s[0][0] += a0 * b0; s[0][1] += a0 * b1; s[0][2] += a0 * b2; s[0][3] += a0 * b3;
            s[1][0] += a1 * b0; s[1][1] += a1 * b1; s[1][2] += a1 * b2; s[1][3] += a1 * b3;
            s[2][0] += a2 * b0; s[2][1] += a2 * b1; s[2][2] += a2 * b2; s[2][3] += a2 * b3;
            s[3][0] += a3 * b0; s[3][1] += a3 * b1; s[3][2] += a3 * b2; s[3][3] += a3 * b3;
        }

        // mask + scale
        bool keep[4][4];
#pragma unroll
        for (int r = 0; r < 4; r++) {
            int row = q0 + ty * 4 + r;
            uint32_t word = g_mask[row * (T_ / 32) + ((kt * 64 + tx * 4) >> 5)];
#pragma unroll
            for (int c = 0; c < 4; c++) {
                int j = kt * 64 + tx * 4 + c;
                keep[r][c] = (word >> (j & 31)) & 1u;
                s[r][c] = keep[r][c] ? s[r][c] * scale : NEG_INF_;
            }
        }

        // online softmax update (row split across the 16 tx lanes of a half-warp)
#pragma unroll
        for (int r = 0; r < 4; r++) {
            float tm = fmaxf(fmaxf(s[r][0], s[r][1]), fmaxf(s[r][2], s[r][3]));
#pragma unroll
            for (int o = 1; o < 16; o <<= 1)
                tm = fmaxf(tm, __shfl_xor_sync(0xffffffffu, tm, o));
            float mn = fmaxf(mr[r], tm);
            // masked entries contribute exactly 0 (guards the fully-masked-tile case)
            float p0 = keep[r][0] ? expf(s[r][0] - mn) : 0.f;
            float p1 = keep[r][1] ? expf(s[r][1] - mn) : 0.f;
            float p2 = keep[r][2] ? expf(s[r][2] - mn) : 0.f;
            float p3 = keep[r][3] ? expf(s[r][3] - mn) : 0.f;
            float ts = p0 + p1 + p2 + p3;
#pragma unroll
            for (int o = 1; o < 16; o <<= 1)
                ts += __shfl_xor_sync(0xffffffffu, ts, o);
            float f = expf(mr[r] - mn);
            lr[r] = lr[r] * f + ts;
            mr[r] = mn;
            acc[r][0] *= f; acc[r][1] *= f;
            Ps[ty * 4 + r][tx * 4 + 0] = p0;
            Ps[ty * 4 + r][tx * 4 + 1] = p1;
            Ps[ty * 4 + r][tx * 4 + 2] = p2;
            Ps[ty * 4 + r][tx * 4 + 3] = p3;
        }
        __syncthreads();

        // O += P @ V   (each thread: 4 rows x 2 dims)
#pragma unroll 4
        for (int j = 0; j < 64; j++) {
            float v0 = Vs[j][tx * 2 + 0];
            float v1 = Vs[j][tx * 2 + 1];
#pragma unroll
            for (int r = 0; r < 4; r++) {
                float p = Ps[ty * 4 + r][j];
                acc[r][0] += p * v0;
                acc[r][1] += p * v1;
            }
        }
        __syncthreads();
    }

    int b = bh >> 4, h = bh & 15;
#pragma unroll
    for (int r = 0; r < 4; r++) {
        int row = q0 + ty * 4 + r;
        float inv = 1.0f / lr[r];
        float* dst = &g_ao[((size_t)(b * T_ + row)) * C_ + h * HD_ + tx * 2];
        dst[0] = acc[r][0] * inv;
        dst[1] = acc[r][1] * inv;
    }
}

// ---------------- launch ----------------
extern "C" void kernel_launch(void* const* d_in, const int* in_sizes, int n_in,
                              void* d_out, int out_size) {
    const float* x    = (const float*)d_in[0];
    const float* Wq   = (const float*)d_in[1];
    const float* Wk   = (const float*)d_in[2];
    const float* Wv   = (const float*)d_in[3];
    const float* Wo   = (const float*)d_in[4];
    const float* grad = (const float*)d_in[5];
    float* out = (float*)d_out;

    float *pq, *pk, *pv, *pao;
    cudaGetSymbolAddress((void**)&pq, g_q);
    cudaGetSymbolAddress((void**)&pk, g_k);
    cudaGetSymbolAddress((void**)&pv, g_v);
    cudaGetSymbolAddress((void**)&pao, g_ao);

    int base_conn = (int)((double)T_ * (1.0 - 0.3));
    int n_extra = base_conn - 3;
    if (n_extra < 0) n_extra = 0;

    logw_kernel<<<1, 256>>>(grad);
    mask_kernel<<<T_, 256>>>(n_extra);

    dim3 gg(C_ / 64, (B_ * T_) / 64);   // (8, 64)
    gemm_kernel<<<gg, 256>>>(x, Wq, pq, 1);
    gemm_kernel<<<gg, 256>>>(x, Wk, pk, 1);
    gemm_kernel<<<gg, 256>>>(x, Wv, pv, 1);

    dim3 ga(T_ / 64, B_ * H_);          // (32, 32)
    attn_kernel<<<ga, 256>>>();

    gemm_kernel<<<gg, 256>>>(pao, Wo, out, 0);
}

// round 7
// speedup vs baseline: 1.0055x; 1.0055x over previous
#include <cuda_runtime.h>
#include <cstdint>
#include <math.h>

#define T_ 2048
#define B_ 2
#define C_ 512
#define H_ 16
#define HD_ 32
#define NEG_INF_ (-1e30f)

// ---------------- scratch (device globals; no allocation allowed) ----------------
__device__ float    g_logw[T_];
__device__ uint32_t g_mask[T_ * (T_ / 32)];
__device__ float    g_q[B_ * H_ * T_ * HD_];
__device__ float    g_k[B_ * H_ * T_ * HD_];
__device__ float    g_v[B_ * H_ * T_ * HD_];
__device__ float    g_ao[B_ * T_ * C_];

// ---------------- threefry2x32 (exact JAX replication) ----------------
__device__ __forceinline__ uint32_t rotl32(uint32_t v, int r) {
    return (v << r) | (v >> (32 - r));
}

__device__ __forceinline__ void threefry2x32(uint32_t k0, uint32_t k1,
                                             uint32_t& x0, uint32_t& x1) {
    uint32_t k2 = k0 ^ k1 ^ 0x1BD11BDAu;
    x0 += k0; x1 += k1;
#define RND_(r) { x0 += x1; x1 = rotl32(x1, (r)); x1 ^= x0; }
    RND_(13) RND_(15) RND_(26) RND_(6)
    x0 += k1; x1 += k2 + 1u;
    RND_(17) RND_(29) RND_(16) RND_(24)
    x0 += k2; x1 += k0 + 2u;
    RND_(13) RND_(15) RND_(26) RND_(6)
    x0 += k0; x1 += k1 + 3u;
    RND_(17) RND_(29) RND_(16) RND_(24)
    x0 += k1; x1 += k2 + 4u;
    RND_(13) RND_(15) RND_(26) RND_(6)
    x0 += k2; x1 += k0 + 5u;
#undef RND_
}

// ---------------- kernel 0: logw = log(softmax(grad*100)) ----------------
__global__ void logw_kernel(const float* __restrict__ grad) {
    __shared__ float red[256];
    int t = threadIdx.x;
    float m = -3.4e38f;
    for (int j = t; j < T_; j += 256) m = fmaxf(m, grad[j] * 100.0f);
    red[t] = m; __syncthreads();
    for (int s = 128; s > 0; s >>= 1) {
        if (t < s) red[t] = fmaxf(red[t], red[t + s]);
        __syncthreads();
    }
    m = red[0]; __syncthreads();
    float sum = 0.f;
    for (int j = t; j < T_; j += 256) sum += expf(grad[j] * 100.0f - m);
    red[t] = sum; __syncthreads();
    for (int s = 128; s > 0; s >>= 1) {
        if (t < s) red[t] += red[t + s];
        __syncthreads();
    }
    sum = red[0];
    for (int j = t; j < T_; j += 256) {
        float p = expf(grad[j] * 100.0f - m) / sum;
        g_logw[j] = logf(p);
    }
}

// ---------------- kernel 1: per-row gumbel top-k mask (exact, partitionable threefry) ----------------
__global__ void mask_kernel(int n_extra) {
    __shared__ uint32_t sk[T_];
    __shared__ uint32_t hist[256];
    __shared__ uint32_t mbits[T_ / 32];
    __shared__ uint32_t s_prefix;
    __shared__ int s_krem;

    int i = blockIdx.x;      // query row
    int t = threadIdx.x;

    // ordered-uint keys of logw + gumbel (band -> -inf)
    for (int j = t; j < T_; j += 256) {
        int dd = j - i;
        float val;
        if (dd >= -1 && dd <= 1) {
            val = -INFINITY;
        } else {
            // JAX partitionable threefry random_bits:
            //   counts = iota(u64);  (x0,x1) = (hi32, lo32) = (0, m)
            //   bits32 = out0 ^ out1
            uint32_t m = (uint32_t)i * (uint32_t)T_ + (uint32_t)j;
            uint32_t a = 0u;
            uint32_t b = m;
            threefry2x32(0u, 42u, a, b);
            uint32_t bits = a ^ b;
            uint32_t fb = (bits >> 9) | 0x3f800000u;
            float f = __uint_as_float(fb) - 1.0f;
            float u = fmaxf(1.17549435e-38f, f);   // jax uniform(minval=tiny)
            float g = -logf(-logf(u));
            val = g_logw[j] + g;
        }
        uint32_t ob = __float_as_uint(val);
        ob = (ob & 0x80000000u) ? ~ob : (ob | 0x80000000u);
        sk[j] = ob;
    }
    for (int w = t; w < T_ / 32; w += 256) mbits[w] = 0u;
    __syncthreads();

    // radix-select the n_extra-th largest key
    uint32_t prefix = 0u, pmask = 0u;
    int krem = n_extra;
    for (int shift = 24; shift >= 0; shift -= 8) {
        hist[t] = 0u;
        __syncthreads();
        for (int j = t; j < T_; j += 256) {
            uint32_t key = sk[j];
            if ((key & pmask) == prefix)
                atomicAdd(&hist[(key >> shift) & 0xFFu], 1u);
        }
        __syncthreads();
        if (t == 0) {
            int acc = 0; int d = 255;
            for (; d > 0; d--) {
                int h = (int)hist[d];
                if (acc + h >= krem) break;
                acc += h;
            }
            s_prefix = prefix | ((uint32_t)d << shift);
            s_krem = krem - acc;
        }
        __syncthreads();
        prefix = s_prefix; krem = s_krem;
        pmask |= (0xFFu << shift);
        __syncthreads();
    }
    uint32_t vstar = prefix;

    // mark strictly-greater values + band, apply causal
    for (int j = t; j < T_; j += 256) {
        int dd = j - i;
        bool band = (dd >= -1 && dd <= 1);
        if ((band || sk[j] > vstar) && j <= i)
            atomicOr(&mbits[j >> 5], 1u << (j & 31));
    }
    __syncthreads();
    // stable (lower-index-first) selection among ties at the threshold
    if (t == 0) {
        int need = krem;
        for (int j = 0; j < T_ && need > 0; j++) {
            if (sk[j] == vstar) {
                need--;
                if (j <= i) mbits[j >> 5] |= (1u << (j & 31));
            }
        }
    }
    __syncthreads();
    for (int w = t; w < T_ / 32; w += 256)
        g_mask[i * (T_ / 32) + w] = mbits[w];
}

// ---------------- kernel 2: tiled fp32 GEMM Y[4096,512] = X[4096,512] @ W[512,512] ----------------
// mode 0: Y row-major [M,C].  mode 1: scatter to [B,H,T,HD] layout.
__global__ void gemm_kernel(const float* __restrict__ X, const float* __restrict__ W,
                            float* __restrict__ Y, int mode) {
    __shared__ float Xs[64][17];
    __shared__ __align__(16) float Ws[16][64];
    int tid = threadIdx.x;
    int tx = tid & 15, ty = tid >> 4;
    int m0 = blockIdx.y * 64, n0 = blockIdx.x * 64;

    float acc[4][4] = {};

    for (int k0 = 0; k0 < C_; k0 += 16) {
        for (int idx = tid; idx < 64 * 16; idx += 256) {
            int r = idx >> 4, c = idx & 15;
            Xs[r][c] = X[(size_t)(m0 + r) * C_ + k0 + c];
        }
        for (int idx = tid; idx < 16 * 64; idx += 256) {
            int r = idx >> 6, c = idx & 63;
            Ws[r][c] = W[(size_t)(k0 + r) * C_ + n0 + c];
        }
        __syncthreads();
#pragma unroll
        for (int kk = 0; kk < 16; kk++) {
            float a0 = Xs[ty * 4 + 0][kk];
            float a1 = Xs[ty * 4 + 1][kk];
            float a2 = Xs[ty * 4 + 2][kk];
            float a3 = Xs[ty * 4 + 3][kk];
            float4 b4 = *(const float4*)&Ws[kk][tx * 4];
            float b[4] = {b4.x, b4.y, b4.z, b4.w};
#pragma unroll
            for (int c = 0; c < 4; c++) {
                acc[0][c] += a0 * b[c];
                acc[1][c] += a1 * b[c];
                acc[2][c] += a2 * b[c];
                acc[3][c] += a3 * b[c];
            }
        }
        __syncthreads();
    }

#pragma unroll
    for (int r = 0; r < 4; r++) {
#pragma unroll
        for (int c = 0; c < 4; c++) {
            int m = m0 + ty * 4 + r;
            int n = n0 + tx * 4 + c;
            if (mode == 1) {
                int b = m >> 11;           // m / T_
                int tt = m & (T_ - 1);
                int h = n >> 5;            // n / HD_
                int d = n & (HD_ - 1);
                Y[(((size_t)(b * H_ + h)) * T_ + tt) * HD_ + d] = acc[r][c];
            } else {
                Y[(size_t)m * C_ + n] = acc[r][c];
            }
        }
    }
}

// ---------------- kernel 3: masked flash attention (fp32) ----------------
__global__ void attn_kernel() {
    int qt = blockIdx.x;       // query tile (64 queries)
    int bh = blockIdx.y;       // b*H + h
    const float* qp = g_q + (size_t)bh * T_ * HD_ + (size_t)qt * 64 * HD_;
    const float* kp = g_k + (size_t)bh * T_ * HD_;
    const float* vp = g_v + (size_t)bh * T_ * HD_;

    __shared__ float Qs[64][33];
    __shared__ float Ks[64][33];
    __shared__ float Vs[64][33];
    __shared__ float Ps[64][65];

    int tid = threadIdx.x;
    int tx = tid & 15, ty = tid >> 4;

    for (int idx = tid; idx < 64 * 32; idx += 256)
        Qs[idx >> 5][idx & 31] = qp[idx];

    float acc[4][2] = {};
    float mr[4], lr[4];
#pragma unroll
    for (int r = 0; r < 4; r++) { mr[r] = NEG_INF_; lr[r] = 0.f; }

    const float scale = 0.17677669529663687f;  // 1/sqrt(32)
    int q0 = qt * 64;

    for (int kt = 0; kt <= qt; kt++) {
        for (int idx = tid; idx < 64 * 32; idx += 256) {
            int j = idx >> 5, d = idx & 31;
            Ks[j][d] = kp[(size_t)(kt * 64) * HD_ + idx];
            Vs[j][d] = vp[(size_t)(kt * 64) * HD_ + idx];
        }
        __syncthreads();

        float s[4][4] = {};
#pragma unroll
        for (int d = 0; d < 32; d++) {
            float a0 = Qs[ty * 4 + 0][d];
            float a1 = Qs[ty * 4 + 1][d];
            float a2 = Qs[ty * 4 + 2][d];
            float a3 = Qs[ty * 4 + 3][d];
            float b0 = Ks[tx * 4 + 0][d];
            float b1 = Ks[tx * 4 + 1][d];
            float b2 = Ks[tx * 4 + 2][d];
            float b3 = Ks[tx * 4 + 3][d];
            s[0][0] += a0 * b0; s[0][1] += a0 * b1; s[0][2] += a0 * b2; s[0][3] += a0 * b3;
            s[1][0] += a1 * b0; s[1][1] += a1 * b1; s[1][2] += a1 * b2; s[1][3] += a1 * b3;
            s[2][0] += a2 * b0; s[2][1] += a2 * b1; s[2][2] += a2 * b2; s[2][3] += a2 * b3;
            s[3][0] += a3 * b0; s[3][1] += a3 * b1; s[3][2] += a3 * b2; s[3][3] += a3 * b3;
        }

        // mask + scale
        bool keep[4][4];
#pragma unroll
        for (int r = 0; r < 4; r++) {
            int row = q0 + ty * 4 + r;
            uint32_t word = g_mask[row * (T_ / 32) + ((kt * 64 + tx * 4) >> 5)];
#pragma unroll
            for (int c = 0; c < 4; c++) {
                int j = kt * 64 + tx * 4 + c;
                keep[r][c] = (word >> (j & 31)) & 1u;
                s[r][c] = keep[r][c] ? s[r][c] * scale : NEG_INF_;
            }
        }

        // online softmax update (row split across the 16 tx lanes of a half-warp)
#pragma unroll
        for (int r = 0; r < 4; r++) {
            float tm = fmaxf(fmaxf(s[r][0], s[r][1]), fmaxf(s[r][2], s[r][3]));
#pragma unroll
            for (int o = 1; o < 16; o <<= 1)
                tm = fmaxf(tm, __shfl_xor_sync(0xffffffffu, tm, o));
            float mn = fmaxf(mr[r], tm);
            // masked entries contribute exactly 0 (guards the fully-masked-tile case)
            float p0 = keep[r][0] ? expf(s[r][0] - mn) : 0.f;
            float p1 = keep[r][1] ? expf(s[r][1] - mn) : 0.f;
            float p2 = keep[r][2] ? expf(s[r][2] - mn) : 0.f;
            float p3 = keep[r][3] ? expf(s[r][3] - mn) : 0.f;
            float ts = p0 + p1 + p2 + p3;
#pragma unroll
            for (int o = 1; o < 16; o <<= 1)
                ts += __shfl_xor_sync(0xffffffffu, ts, o);
            float f = expf(mr[r] - mn);
            lr[r] = lr[r] * f + ts;
            mr[r] = mn;
            acc[r][0] *= f; acc[r][1] *= f;
            Ps[ty * 4 + r][tx * 4 + 0] = p0;
            Ps[ty * 4 + r][tx * 4 + 1] = p1;
            Ps[ty * 4 + r][tx * 4 + 2] = p2;
            Ps[ty * 4 + r][tx * 4 + 3] = p3;
        }
        __syncthreads();

        // O += P @ V   (each thread: 4 rows x 2 dims)
#pragma unroll 4
        for (int j = 0; j < 64; j++) {
            float v0 = Vs[j][tx * 2 + 0];
            float v1 = Vs[j][tx * 2 + 1];
#pragma unroll
            for (int r = 0; r < 4; r++) {
                float p = Ps[ty * 4 + r][j];
                acc[r][0] += p * v0;
                acc[r][1] += p * v1;
            }
        }
        __syncthreads();
    }

    int b = bh >> 4, h = bh & 15;
#pragma unroll
    for (int r = 0; r < 4; r++) {
        int row = q0 + ty * 4 + r;
        float inv = 1.0f / lr[r];
        float* dst = &g_ao[((size_t)(b * T_ + row)) * C_ + h * HD_ + tx * 2];
        dst[0] = acc[r][0] * inv;
        dst[1] = acc[r][1] * inv;
    }
}

// ---------------- launch ----------------
extern "C" void kernel_launch(void* const* d_in, const int* in_sizes, int n_in,
                              void* d_out, int out_size) {
    const float* x    = (const float*)d_in[0];
    const float* Wq   = (const float*)d_in[1];
    const float* Wk   = (const float*)d_in[2];
    const float* Wv   = (const float*)d_in[3];
    const float* Wo   = (const float*)d_in[4];
    const float* grad = (const float*)d_in[5];
    float* out = (float*)d_out;

    float *pq, *pk, *pv, *pao;
    cudaGetSymbolAddress((void**)&pq, g_q);
    cudaGetSymbolAddress((void**)&pk, g_k);
    cudaGetSymbolAddress((void**)&pv, g_v);
    cudaGetSymbolAddress((void**)&pao, g_ao);

    int base_conn = (int)((double)T_ * (1.0 - 0.3));
    int n_extra = base_conn - 3;
    if (n_extra < 0) n_extra = 0;

    logw_kernel<<<1, 256>>>(grad);
    mask_kernel<<<T_, 256>>>(n_extra);

    dim3 gg(C_ / 64, (B_ * T_) / 64);   // (8, 64)
    gemm_kernel<<<gg, 256>>>(x, Wq, pq, 1);
    gemm_kernel<<<gg, 256>>>(x, Wk, pk, 1);
    gemm_kernel<<<gg, 256>>>(x, Wv, pv, 1);

    dim3 ga(T_ / 64, B_ * H_);          // (32, 32)
    attn_kernel<<<ga, 256>>>();

    gemm_kernel<<<gg, 256>>>(pao, Wo, out, 0);
}